// round 1
// baseline (speedup 1.0000x reference)
#include <cuda_runtime.h>
#include <cstdint>

// Problem dims (fixed by the reference)
#define SEQL   2048
#define NMODEL 4096
#define HEADS  32
#define DHEAD  128
#define MCACHE 4096

// ---------------- scratch (device globals; no allocs allowed) ----------------
__device__ float g_Q[(size_t)HEADS * SEQL * DHEAD];     // 32 MB  [h][s][d]
__device__ float g_K[(size_t)HEADS * MCACHE * DHEAD];   // 64 MB  [h][m][d]
__device__ float g_V[(size_t)HEADS * MCACHE * DHEAD];   // 64 MB  [h][m][d]

// ---------------- 0) copy caches into scratch ----------------
__global__ void copy_cache_kernel(const float4* __restrict__ cK,
                                  const float4* __restrict__ cV) {
    const int n = HEADS * MCACHE * DHEAD / 4;  // 4,194,304 float4
    float4* dK = reinterpret_cast<float4*>(g_K);
    float4* dV = reinterpret_cast<float4*>(g_V);
    for (int i = blockIdx.x * blockDim.x + threadIdx.x; i < n;
         i += gridDim.x * blockDim.x) {
        dK[i] = cK[i];
        dV[i] = cV[i];
    }
}

// ---------------- 1) fused QKV GEMM: C = X @ W{q,k,v} ----------------
// 128x128x16 tile, 256 threads, 8x8 micro-tile, fp32.
// blockIdx.z: 0=Q, 1=K, 2=V.  Since BN==DHEAD, h = blockIdx.x, d = tx*8+j.
#define BM 128
#define BN 128
#define BKK 16
__global__ void __launch_bounds__(256)
qkv_gemm_kernel(const float* __restrict__ X,
                const float* __restrict__ Wq,
                const float* __restrict__ Wk,
                const float* __restrict__ Wv,
                const int* __restrict__ Pp) {
    __shared__ float As[BKK][132];   // transposed A tile, pad keeps STS 2-way max, LDS128-aligned
    __shared__ float Bs[BKK][BN];

    const int z = blockIdx.z;
    const float* __restrict__ W = (z == 0) ? Wq : ((z == 1) ? Wk : Wv);
    const int brow = blockIdx.y * BM;     // s base
    const int h    = blockIdx.x;          // head (BN == DHEAD)
    const int bcol = h * BN;               // n base
    const int t  = threadIdx.x;
    const int tx = t & 15, ty = t >> 4;

    // load assignments
    const int arow  = t >> 2;          // 0..63
    const int acol4 = (t & 3) * 4;     // 0,4,8,12
    const int bkrow = t >> 5;          // 0..7
    const int bcol4 = (t & 31) * 4;    // 0..124

    const int P = *Pp;                  // uniform

    float acc[8][8];
#pragma unroll
    for (int i = 0; i < 8; i++)
#pragma unroll
        for (int j = 0; j < 8; j++) acc[i][j] = 0.f;

    const float* Ag = X + (size_t)brow * NMODEL;

    for (int k0 = 0; k0 < NMODEL; k0 += BKK) {
        // A tile 128x16 -> As[k][m] (transposed)
#pragma unroll
        for (int r = 0; r < 2; r++) {
            const int m = arow + r * 64;
            const float4 va = *reinterpret_cast<const float4*>(
                Ag + (size_t)m * NMODEL + k0 + acol4);
            As[acol4 + 0][m] = va.x;
            As[acol4 + 1][m] = va.y;
            As[acol4 + 2][m] = va.z;
            As[acol4 + 3][m] = va.w;
        }
        // B tile 16x128 -> Bs[k][n]
#pragma unroll
        for (int r = 0; r < 2; r++) {
            const int kk = bkrow + r * 8;
            *reinterpret_cast<float4*>(&Bs[kk][bcol4]) =
                *reinterpret_cast<const float4*>(
                    W + (size_t)(k0 + kk) * NMODEL + bcol + bcol4);
        }
        __syncthreads();

#pragma unroll
        for (int kk = 0; kk < BKK; kk++) {
            float a[8], b[8];
            *reinterpret_cast<float4*>(&a[0]) = *reinterpret_cast<const float4*>(&As[kk][ty * 8]);
            *reinterpret_cast<float4*>(&a[4]) = *reinterpret_cast<const float4*>(&As[kk][ty * 8 + 4]);
            *reinterpret_cast<float4*>(&b[0]) = *reinterpret_cast<const float4*>(&Bs[kk][tx * 8]);
            *reinterpret_cast<float4*>(&b[4]) = *reinterpret_cast<const float4*>(&Bs[kk][tx * 8 + 4]);
#pragma unroll
            for (int i = 0; i < 8; i++)
#pragma unroll
                for (int j = 0; j < 8; j++) acc[i][j] += a[i] * b[j];
        }
        __syncthreads();
    }

    // write out: Q -> g_Q[h][s][d]; K/V -> cache scratch rows P+s
#pragma unroll
    for (int i = 0; i < 8; i++) {
        const int s = brow + ty * 8 + i;
        float* dst;
        if (z == 0)      dst = g_Q + ((size_t)h * SEQL + s) * DHEAD + tx * 8;
        else if (z == 1) dst = g_K + ((size_t)h * MCACHE + P + s) * DHEAD + tx * 8;
        else             dst = g_V + ((size_t)h * MCACHE + P + s) * DHEAD + tx * 8;
        *reinterpret_cast<float4*>(dst) =
            make_float4(acc[i][0], acc[i][1], acc[i][2], acc[i][3]);
        *reinterpret_cast<float4*>(dst + 4) =
            make_float4(acc[i][4], acc[i][5], acc[i][6], acc[i][7]);
    }
}

// ---------------- 2) flash attention, fp32, no scale, full cache ----------------
// Block: (head, 64-query tile). 256 threads, tx = t%16, ty = t/16.
// Scores micro-tile 4q x 4k per thread; AV micro-tile 4q x 8d per thread.
#define AT_BQ 64
#define AT_BK 64
#define QS_LD 68    // [d][q] transposed, pad 64->68 (float4-aligned, conflict-free)
#define VS_LD 132   // [k][d] natural,   pad 128->132
#define PS_LD 68
#define ATT_SMEM_FLOATS (128 * QS_LD /*Qs*/ + 128 * QS_LD /*Ks|Vs*/ + AT_BK * PS_LD /*Ps*/)
#define ATT_SMEM_BYTES (ATT_SMEM_FLOATS * 4)

__global__ void __launch_bounds__(256)
attn_kernel(float* __restrict__ out) {
    extern __shared__ float sm[];
    float* Qs  = sm;                       // [128][QS_LD]  (d-major)
    float* KVs = sm + 128 * QS_LD;         // Ks [128][QS_LD] then reused as Vs [64][VS_LD]
    float* Ps  = sm + 2 * 128 * QS_LD;     // [64][PS_LD]

    const int h     = blockIdx.y;
    const int qbase = blockIdx.x * AT_BQ;
    const int t    = threadIdx.x;
    const int tx   = t & 15, ty = t >> 4;
    const int w    = t >> 5, lane = t & 31;

    const float* __restrict__ Qg = g_Q + ((size_t)h * SEQL + qbase) * DHEAD;
    const float* __restrict__ Kg = g_K + (size_t)h * MCACHE * DHEAD;
    const float* __restrict__ Vg = g_V + (size_t)h * MCACHE * DHEAD;

    // Load Q (64 x 128) transposed into Qs[d][q]. Lane traverses q so STS is conflict-free.
    {
        const int q   = lane + 32 * (w & 1);
        const int dq0 = (w >> 1);  // 0..3
        const float* src = Qg + (size_t)q * DHEAD;
#pragma unroll
        for (int r = 0; r < 8; r++) {
            const int dq = dq0 + 4 * r;
            const float4 v = *reinterpret_cast<const float4*>(src + dq * 4);
            Qs[(dq * 4 + 0) * QS_LD + q] = v.x;
            Qs[(dq * 4 + 1) * QS_LD + q] = v.y;
            Qs[(dq * 4 + 2) * QS_LD + q] = v.z;
            Qs[(dq * 4 + 3) * QS_LD + q] = v.w;
        }
    }

    float m_[4], l_[4], acc[4][8];
#pragma unroll
    for (int i = 0; i < 4; i++) {
        m_[i] = -1e30f; l_[i] = 0.f;
#pragma unroll
        for (int j = 0; j < 8; j++) acc[i][j] = 0.f;
    }

    for (int kb = 0; kb < MCACHE; kb += AT_BK) {
        __syncthreads();  // prior AV reads of KVs done (and Q STS ordered on 1st iter)

        // Load K tile (64 x 128) transposed into KVs[d][k]
        {
            const int k   = lane + 32 * (w & 1);
            const int dq0 = (w >> 1);
            const float* src = Kg + (size_t)(kb + k) * DHEAD;
#pragma unroll
            for (int r = 0; r < 8; r++) {
                const int dq = dq0 + 4 * r;
                const float4 v = *reinterpret_cast<const float4*>(src + dq * 4);
                KVs[(dq * 4 + 0) * QS_LD + k] = v.x;
                KVs[(dq * 4 + 1) * QS_LD + k] = v.y;
                KVs[(dq * 4 + 2) * QS_LD + k] = v.z;
                KVs[(dq * 4 + 3) * QS_LD + k] = v.w;
            }
        }
        __syncthreads();

        // Scores: s[4][4] = Q[qrows] . K[kcols]   (no softmax scale in reference)
        float s[4][4];
#pragma unroll
        for (int i = 0; i < 4; i++)
#pragma unroll
            for (int j = 0; j < 4; j++) s[i][j] = 0.f;

#pragma unroll 4
        for (int d = 0; d < DHEAD; d++) {
            float a[4], b[4];
            *reinterpret_cast<float4*>(a) =
                *reinterpret_cast<const float4*>(&Qs[d * QS_LD + ty * 4]);
            *reinterpret_cast<float4*>(b) =
                *reinterpret_cast<const float4*>(&KVs[d * QS_LD + tx * 4]);
#pragma unroll
            for (int i = 0; i < 4; i++)
#pragma unroll
                for (int j = 0; j < 4; j++) s[i][j] += a[i] * b[j];
        }

        // Online softmax (rows owned by 16 lanes sharing ty; reduce over lane^{1,2,4,8})
#pragma unroll
        for (int i = 0; i < 4; i++) {
            float v = fmaxf(fmaxf(s[i][0], s[i][1]), fmaxf(s[i][2], s[i][3]));
#pragma unroll
            for (int o = 8; o >= 1; o >>= 1)
                v = fmaxf(v, __shfl_xor_sync(0xffffffffu, v, o));
            const float newm = fmaxf(m_[i], v);
            const float corr = __expf(m_[i] - newm);
            float rs = 0.f;
#pragma unroll
            for (int j = 0; j < 4; j++) {
                const float p = __expf(s[i][j] - newm);
                s[i][j] = p;
                rs += p;
            }
#pragma unroll
            for (int o = 8; o >= 1; o >>= 1)
                rs += __shfl_xor_sync(0xffffffffu, rs, o);
            l_[i] = l_[i] * corr + rs;
            m_[i] = newm;
#pragma unroll
            for (int j = 0; j < 8; j++) acc[i][j] *= corr;
        }

        // stage P tile
#pragma unroll
        for (int i = 0; i < 4; i++)
            *reinterpret_cast<float4*>(&Ps[(ty * 4 + i) * PS_LD + tx * 4]) =
                make_float4(s[i][0], s[i][1], s[i][2], s[i][3]);

        __syncthreads();  // Ks fully consumed, Ps fully written

        // Load V tile (64 x 128) natural into KVs[k][d] (coalesced, conflict-free)
        {
#pragma unroll
            for (int r = 0; r < 8; r++) {
                const int k = w + 8 * r;
                const float4 v = *reinterpret_cast<const float4*>(
                    Vg + (size_t)(kb + k) * DHEAD + lane * 4);
                *reinterpret_cast<float4*>(&KVs[k * VS_LD + lane * 4]) = v;
            }
        }
        __syncthreads();

        // acc += P @ V
#pragma unroll 4
        for (int kk = 0; kk < AT_BK; kk++) {
            float p[4];
#pragma unroll
            for (int i = 0; i < 4; i++) p[i] = Ps[(ty * 4 + i) * PS_LD + kk];
            float vv[8];
            *reinterpret_cast<float4*>(&vv[0]) =
                *reinterpret_cast<const float4*>(&KVs[kk * VS_LD + tx * 8]);
            *reinterpret_cast<float4*>(&vv[4]) =
                *reinterpret_cast<const float4*>(&KVs[kk * VS_LD + tx * 8 + 4]);
#pragma unroll
            for (int i = 0; i < 4; i++)
#pragma unroll
                for (int j = 0; j < 8; j++) acc[i][j] += p[i] * vv[j];
        }
    }

    // Normalize and write. out flat = h*SEQL*DHEAD + s*DHEAD + d  (matches reshape(S, H*D))
#pragma unroll
    for (int i = 0; i < 4; i++) {
        const float inv = 1.f / l_[i];
        const int q = qbase + ty * 4 + i;
        float* o = out + (size_t)h * SEQL * DHEAD + (size_t)q * DHEAD + tx * 8;
        *reinterpret_cast<float4*>(o) =
            make_float4(acc[i][0] * inv, acc[i][1] * inv, acc[i][2] * inv, acc[i][3] * inv);
        *reinterpret_cast<float4*>(o + 4) =
            make_float4(acc[i][4] * inv, acc[i][5] * inv, acc[i][6] * inv, acc[i][7] * inv);
    }
}

// ---------------- launch ----------------
extern "C" void kernel_launch(void* const* d_in, const int* in_sizes, int n_in,
                              void* d_out, int out_size) {
    const float* X  = (const float*)d_in[0];
    const float* Wq = (const float*)d_in[1];
    const float* Wk = (const float*)d_in[2];
    const float* Wv = (const float*)d_in[3];
    const float* cK = (const float*)d_in[4];
    const float* cV = (const float*)d_in[5];
    const int*   Pp = (const int*)d_in[6];

    // 0) caches -> scratch (full copy; GEMM overwrites rows [P, P+S) afterwards)
    copy_cache_kernel<<<1024, 256>>>((const float4*)cK, (const float4*)cV);

    // 1) QKV projections + cache write
    dim3 ggrid(NMODEL / BN, SEQL / BM, 3);
    qkv_gemm_kernel<<<ggrid, 256>>>(X, Wq, Wk, Wv, Pp);

    // 2) attention (dynamic smem 87,040 B)
    cudaFuncSetAttribute(attn_kernel, cudaFuncAttributeMaxDynamicSharedMemorySize,
                         ATT_SMEM_BYTES);
    dim3 agrid(SEQL / AT_BQ, HEADS);
    attn_kernel<<<agrid, 256, ATT_SMEM_BYTES>>>((float*)d_out);
}

// round 3
// speedup vs baseline: 1.4448x; 1.4448x over previous
#include <cuda_runtime.h>
#include <cuda_bf16.h>
#include <cstdint>

// Problem dims (fixed by the reference)
#define SEQL   2048
#define NMODEL 4096
#define HEADS  32
#define DHEAD  128
#define MCACHE 4096

// ======================= family-portable PTX helpers =======================
__device__ __forceinline__ uint32_t smem_to_u32(const void* p) {
    uint32_t a;
    asm("{ .reg .u64 t; cvta.to.shared.u64 t, %1; cvt.u32.u64 %0, t; }"
        : "=r"(a) : "l"(p));
    return a;
}
__device__ __forceinline__ void mma_bf16(float* c, const uint32_t* a, const uint32_t* b) {
    asm volatile(
        "mma.sync.aligned.m16n8k16.row.col.f32.bf16.bf16.f32 "
        "{%0,%1,%2,%3}, {%4,%5,%6,%7}, {%8,%9}, {%0,%1,%2,%3};"
        : "+f"(c[0]), "+f"(c[1]), "+f"(c[2]), "+f"(c[3])
        : "r"(a[0]), "r"(a[1]), "r"(a[2]), "r"(a[3]), "r"(b[0]), "r"(b[1]));
}
__device__ __forceinline__ void ldmat4(uint32_t* r, uint32_t addr) {
    asm volatile("ldmatrix.sync.aligned.m8n8.x4.shared.b16 {%0,%1,%2,%3}, [%4];"
        : "=r"(r[0]), "=r"(r[1]), "=r"(r[2]), "=r"(r[3]) : "r"(addr));
}
__device__ __forceinline__ void cpasync16(uint32_t dst, const void* src) {
    asm volatile("cp.async.cg.shared.global [%0], [%1], 16;" :: "r"(dst), "l"(src));
}
#define CP_COMMIT() asm volatile("cp.async.commit_group;" ::: "memory")
#define CP_WAIT(n)  asm volatile("cp.async.wait_group %0;" :: "n"(n) : "memory")

// ======================= scratch (device globals) =======================
__device__ float g_Q[(size_t)HEADS * SEQL * DHEAD];
__device__ float g_K[(size_t)HEADS * MCACHE * DHEAD];
__device__ float g_V[(size_t)HEADS * MCACHE * DHEAD];
__device__ __nv_bfloat16 g_Xhi[(size_t)SEQL * NMODEL];
__device__ __nv_bfloat16 g_Xlo[(size_t)SEQL * NMODEL];
__device__ __nv_bfloat16 g_Whi[3][(size_t)NMODEL * NMODEL];  // transposed: [n][k]
__device__ __nv_bfloat16 g_Wlo[3][(size_t)NMODEL * NMODEL];

// ======================= 0) copy caches =======================
__global__ void copy_cache_kernel(const float4* __restrict__ cK,
                                  const float4* __restrict__ cV) {
    const int n = HEADS * MCACHE * DHEAD / 4;
    float4* dK = reinterpret_cast<float4*>(g_K);
    float4* dV = reinterpret_cast<float4*>(g_V);
    for (int i = blockIdx.x * blockDim.x + threadIdx.x; i < n;
         i += gridDim.x * blockDim.x) {
        dK[i] = cK[i];
        dV[i] = cV[i];
    }
}

// ======================= 0b) split X into hi/lo bf16 =======================
__global__ void convert_X_kernel(const float4* __restrict__ X) {
    const int n = SEQL * NMODEL / 4;
    __nv_bfloat162* Hi = reinterpret_cast<__nv_bfloat162*>(g_Xhi);
    __nv_bfloat162* Lo = reinterpret_cast<__nv_bfloat162*>(g_Xlo);
    for (int i = blockIdx.x * blockDim.x + threadIdx.x; i < n;
         i += gridDim.x * blockDim.x) {
        float4 v = X[i];
        __nv_bfloat16 h0 = __float2bfloat16(v.x), h1 = __float2bfloat16(v.y);
        __nv_bfloat16 h2 = __float2bfloat16(v.z), h3 = __float2bfloat16(v.w);
        __nv_bfloat16 l0 = __float2bfloat16(v.x - __bfloat162float(h0));
        __nv_bfloat16 l1 = __float2bfloat16(v.y - __bfloat162float(h1));
        __nv_bfloat16 l2 = __float2bfloat16(v.z - __bfloat162float(h2));
        __nv_bfloat16 l3 = __float2bfloat16(v.w - __bfloat162float(h3));
        Hi[2 * i]     = __nv_bfloat162(h0, h1);
        Hi[2 * i + 1] = __nv_bfloat162(h2, h3);
        Lo[2 * i]     = __nv_bfloat162(l0, l1);
        Lo[2 * i + 1] = __nv_bfloat162(l2, l3);
    }
}

// ======================= 0c) transpose + split W =======================
__global__ void __launch_bounds__(256)
convert_W_kernel(const float* __restrict__ Wq,
                 const float* __restrict__ Wk,
                 const float* __restrict__ Wv) {
    __shared__ float tile[32][33];
    const int z = blockIdx.z;
    const float* __restrict__ W = (z == 0) ? Wq : ((z == 1) ? Wk : Wv);
    const int n0 = blockIdx.x * 32;
    const int k0 = blockIdx.y * 32;
    const int t = threadIdx.x;
    const int tx = t & 31, ty = t >> 5;
#pragma unroll
    for (int i = 0; i < 4; i++)
        tile[ty + 8 * i][tx] = W[(size_t)(k0 + ty + 8 * i) * NMODEL + n0 + tx];
    __syncthreads();
    __nv_bfloat16* Hi = g_Whi[z];
    __nv_bfloat16* Lo = g_Wlo[z];
#pragma unroll
    for (int i = 0; i < 4; i++) {
        const float v = tile[tx][ty + 8 * i];
        const __nv_bfloat16 h = __float2bfloat16(v);
        const __nv_bfloat16 l = __float2bfloat16(v - __bfloat162float(h));
        const size_t o = (size_t)(n0 + ty + 8 * i) * NMODEL + k0 + tx;
        Hi[o] = h;
        Lo[o] = l;
    }
}

// ======================= 1) split-bf16 mma.sync QKV GEMM =======================
// CTA tile 128x128, BK=32 bf16, double-buffered cp.async, 8 warps (2M x 4N),
// warp tile 64x32, m16n8k16, 3 MMAs per k16 (hihi + hilo + lohi).
#define GBM 128
#define GBN 128
#define GBK 32
#define G_ITERS (NMODEL / GBK)       // 128
#define G_STAGE 32768                 // Ahi 8K + Alo 8K + Bhi 8K + Blo 8K
#define G_SMEM  (2 * G_STAGE)

// smem chunk swizzle: row stride 64B, 16B chunk c -> c ^ ((row>>1)&3)
#define SWZ(row, ch) ((uint32_t)((row) * 64 + ((((ch) ^ (((row) >> 1) & 3))) << 4)))

__global__ void __launch_bounds__(256, 1)
qkv_gemm_mma(const int* __restrict__ Pp) {
    extern __shared__ char smg[];
    const uint32_t sb = smem_to_u32(smg);
    const int t = threadIdx.x, lane = t & 31, wid = t >> 5;
    const int mt = blockIdx.x;   // consecutive bids share the same W slab (L2 reuse)
    const int nt = blockIdx.y;
    const int z  = blockIdx.z;
    const int wm = wid & 1;       // warp row (2)
    const int wn = wid >> 1;      // warp col (4)

    const __nv_bfloat16* __restrict__ Ah = g_Xhi + (size_t)(mt * GBM) * NMODEL;
    const __nv_bfloat16* __restrict__ Al = g_Xlo + (size_t)(mt * GBM) * NMODEL;
    const __nv_bfloat16* __restrict__ Bh = g_Whi[z] + (size_t)(nt * GBN) * NMODEL;
    const __nv_bfloat16* __restrict__ Bl = g_Wlo[z] + (size_t)(nt * GBN) * NMODEL;

    float acc[4][4][4];
#pragma unroll
    for (int i = 0; i < 4; i++)
#pragma unroll
        for (int j = 0; j < 4; j++)
#pragma unroll
            for (int r = 0; r < 4; r++) acc[i][j][r] = 0.f;

    // per-thread load slots: idx -> (row, chunk)
    const int r0 = t >> 2, c0 = t & 3;          // idx = t
    const int r1 = (t + 256) >> 2, c1 = t & 3;  // idx = t+256

    // ---- prologue: stage 0 ----
    {
        const int k0 = 0;
        const uint32_t stg = sb;
        size_t ga0 = (size_t)r0 * NMODEL + k0 + c0 * 8;
        size_t ga1 = (size_t)r1 * NMODEL + k0 + c1 * 8;
        cpasync16(stg + SWZ(r0, c0), Ah + ga0);
        cpasync16(stg + SWZ(r1, c1), Ah + ga1);
        cpasync16(stg + 8192 + SWZ(r0, c0), Al + ga0);
        cpasync16(stg + 8192 + SWZ(r1, c1), Al + ga1);
        cpasync16(stg + 16384 + SWZ(r0, c0), Bh + ga0);
        cpasync16(stg + 16384 + SWZ(r1, c1), Bh + ga1);
        cpasync16(stg + 24576 + SWZ(r0, c0), Bl + ga0);
        cpasync16(stg + 24576 + SWZ(r1, c1), Bl + ga1);
        CP_COMMIT();
    }

    // fragment address components (constant over loop)
    const int rowA = wm * 64 + (lane & 7) + ((lane >> 3) & 1) * 8;  // + mi*16
    const int chA  = (lane >> 4);                                    // + 2g
    const int rowB = wn * 32 + (lane & 7) + ((lane & 16) ? 8 : 0);   // + bj*16
    const int chB  = ((lane >> 3) & 1);                              // + 2g

    for (int c = 0; c < G_ITERS; ++c) {
        if (c + 1 < G_ITERS) {
            const int k0 = (c + 1) * GBK;
            const uint32_t stg = sb + ((c + 1) & 1) * G_STAGE;
            size_t ga0 = (size_t)r0 * NMODEL + k0 + c0 * 8;
            size_t ga1 = (size_t)r1 * NMODEL + k0 + c1 * 8;
            cpasync16(stg + SWZ(r0, c0), Ah + ga0);
            cpasync16(stg + SWZ(r1, c1), Ah + ga1);
            cpasync16(stg + 8192 + SWZ(r0, c0), Al + ga0);
            cpasync16(stg + 8192 + SWZ(r1, c1), Al + ga1);
            cpasync16(stg + 16384 + SWZ(r0, c0), Bh + ga0);
            cpasync16(stg + 16384 + SWZ(r1, c1), Bh + ga1);
            cpasync16(stg + 24576 + SWZ(r0, c0), Bl + ga0);
            cpasync16(stg + 24576 + SWZ(r1, c1), Bl + ga1);
            CP_COMMIT();
            CP_WAIT(1);
        } else {
            CP_WAIT(0);
        }
        __syncthreads();

        const uint32_t sA = sb + (c & 1) * G_STAGE;
        const uint32_t sB = sA + 16384;
#pragma unroll
        for (int g = 0; g < 2; ++g) {
            uint32_t ah[4][4], al[4][4], bh[2][4], bl[2][4];
#pragma unroll
            for (int mi = 0; mi < 4; ++mi) {
                const int row = rowA + mi * 16;
                const int ch  = 2 * g + chA;
                const uint32_t ad = sA + SWZ(row, ch);
                ldmat4(ah[mi], ad);
                ldmat4(al[mi], ad + 8192);
            }
#pragma unroll
            for (int bj = 0; bj < 2; ++bj) {
                const int row = rowB + bj * 16;
                const int ch  = 2 * g + chB;
                const uint32_t ad = sB + SWZ(row, ch);
                ldmat4(bh[bj], ad);
                ldmat4(bl[bj], ad + 8192);
            }
#pragma unroll
            for (int mi = 0; mi < 4; ++mi)
#pragma unroll
                for (int nj = 0; nj < 4; ++nj) {
                    const uint32_t* bhp = &bh[nj >> 1][(nj & 1) * 2];
                    const uint32_t* blp = &bl[nj >> 1][(nj & 1) * 2];
                    mma_bf16(acc[mi][nj], ah[mi], bhp);
                    mma_bf16(acc[mi][nj], ah[mi], blp);
                    mma_bf16(acc[mi][nj], al[mi], bhp);
                }
        }
        __syncthreads();
    }

    // ---- epilogue ----
    const int P = *Pp;
    const int qr = lane >> 2, qc = (lane & 3) * 2;
#pragma unroll
    for (int mi = 0; mi < 4; ++mi) {
#pragma unroll
        for (int nj = 0; nj < 4; ++nj) {
            const int m0 = mt * GBM + wm * 64 + mi * 16 + qr;
            const int n  = nt * GBN + wn * 32 + nj * 8 + qc;
            const int h = n >> 7, d0 = n & 127;
            float* base;
            if (z == 0)      base = g_Q + ((size_t)h * SEQL + m0) * DHEAD + d0;
            else if (z == 1) base = g_K + ((size_t)h * MCACHE + P + m0) * DHEAD + d0;
            else             base = g_V + ((size_t)h * MCACHE + P + m0) * DHEAD + d0;
            *reinterpret_cast<float2*>(base) =
                make_float2(acc[mi][nj][0], acc[mi][nj][1]);
            *reinterpret_cast<float2*>(base + (size_t)8 * DHEAD) =
                make_float2(acc[mi][nj][2], acc[mi][nj][3]);
        }
    }
}

// ======================= 2) flash attention, fp32 (unchanged R1) =======================
#define AT_BQ 64
#define AT_BK 64
#define QS_LD 68
#define VS_LD 132
#define PS_LD 68
#define ATT_SMEM_FLOATS (128 * QS_LD + 128 * QS_LD + AT_BK * PS_LD)
#define ATT_SMEM_BYTES (ATT_SMEM_FLOATS * 4)

__global__ void __launch_bounds__(256)
attn_kernel(float* __restrict__ out) {
    extern __shared__ float sm[];
    float* Qs  = sm;
    float* KVs = sm + 128 * QS_LD;
    float* Ps  = sm + 2 * 128 * QS_LD;

    const int h     = blockIdx.y;
    const int qbase = blockIdx.x * AT_BQ;
    const int t    = threadIdx.x;
    const int tx   = t & 15, ty = t >> 4;
    const int w    = t >> 5, lane = t & 31;

    const float* __restrict__ Qg = g_Q + ((size_t)h * SEQL + qbase) * DHEAD;
    const float* __restrict__ Kg = g_K + (size_t)h * MCACHE * DHEAD;
    const float* __restrict__ Vg = g_V + (size_t)h * MCACHE * DHEAD;

    {
        const int q   = lane + 32 * (w & 1);
        const int dq0 = (w >> 1);
        const float* src = Qg + (size_t)q * DHEAD;
#pragma unroll
        for (int r = 0; r < 8; r++) {
            const int dq = dq0 + 4 * r;
            const float4 v = *reinterpret_cast<const float4*>(src + dq * 4);
            Qs[(dq * 4 + 0) * QS_LD + q] = v.x;
            Qs[(dq * 4 + 1) * QS_LD + q] = v.y;
            Qs[(dq * 4 + 2) * QS_LD + q] = v.z;
            Qs[(dq * 4 + 3) * QS_LD + q] = v.w;
        }
    }

    float m_[4], l_[4], acc[4][8];
#pragma unroll
    for (int i = 0; i < 4; i++) {
        m_[i] = -1e30f; l_[i] = 0.f;
#pragma unroll
        for (int j = 0; j < 8; j++) acc[i][j] = 0.f;
    }

    for (int kb = 0; kb < MCACHE; kb += AT_BK) {
        __syncthreads();
        {
            const int k   = lane + 32 * (w & 1);
            const int dq0 = (w >> 1);
            const float* src = Kg + (size_t)(kb + k) * DHEAD;
#pragma unroll
            for (int r = 0; r < 8; r++) {
                const int dq = dq0 + 4 * r;
                const float4 v = *reinterpret_cast<const float4*>(src + dq * 4);
                KVs[(dq * 4 + 0) * QS_LD + k] = v.x;
                KVs[(dq * 4 + 1) * QS_LD + k] = v.y;
                KVs[(dq * 4 + 2) * QS_LD + k] = v.z;
                KVs[(dq * 4 + 3) * QS_LD + k] = v.w;
            }
        }
        __syncthreads();

        float s[4][4];
#pragma unroll
        for (int i = 0; i < 4; i++)
#pragma unroll
            for (int j = 0; j < 4; j++) s[i][j] = 0.f;

#pragma unroll 4
        for (int d = 0; d < DHEAD; d++) {
            float a[4], b[4];
            *reinterpret_cast<float4*>(a) =
                *reinterpret_cast<const float4*>(&Qs[d * QS_LD + ty * 4]);
            *reinterpret_cast<float4*>(b) =
                *reinterpret_cast<const float4*>(&KVs[d * QS_LD + tx * 4]);
#pragma unroll
            for (int i = 0; i < 4; i++)
#pragma unroll
                for (int j = 0; j < 4; j++) s[i][j] += a[i] * b[j];
        }

#pragma unroll
        for (int i = 0; i < 4; i++) {
            float v = fmaxf(fmaxf(s[i][0], s[i][1]), fmaxf(s[i][2], s[i][3]));
#pragma unroll
            for (int o = 8; o >= 1; o >>= 1)
                v = fmaxf(v, __shfl_xor_sync(0xffffffffu, v, o));
            const float newm = fmaxf(m_[i], v);
            const float corr = __expf(m_[i] - newm);
            float rs = 0.f;
#pragma unroll
            for (int j = 0; j < 4; j++) {
                const float p = __expf(s[i][j] - newm);
                s[i][j] = p;
                rs += p;
            }
#pragma unroll
            for (int o = 8; o >= 1; o >>= 1)
                rs += __shfl_xor_sync(0xffffffffu, rs, o);
            l_[i] = l_[i] * corr + rs;
            m_[i] = newm;
#pragma unroll
            for (int j = 0; j < 8; j++) acc[i][j] *= corr;
        }

#pragma unroll
        for (int i = 0; i < 4; i++)
            *reinterpret_cast<float4*>(&Ps[(ty * 4 + i) * PS_LD + tx * 4]) =
                make_float4(s[i][0], s[i][1], s[i][2], s[i][3]);

        __syncthreads();

        {
#pragma unroll
            for (int r = 0; r < 8; r++) {
                const int k = w + 8 * r;
                const float4 v = *reinterpret_cast<const float4*>(
                    Vg + (size_t)(kb + k) * DHEAD + lane * 4);
                *reinterpret_cast<float4*>(&KVs[k * VS_LD + lane * 4]) = v;
            }
        }
        __syncthreads();

#pragma unroll 4
        for (int kk = 0; kk < AT_BK; kk++) {
            float p[4];
#pragma unroll
            for (int i = 0; i < 4; i++) p[i] = Ps[(ty * 4 + i) * PS_LD + kk];
            float vv[8];
            *reinterpret_cast<float4*>(&vv[0]) =
                *reinterpret_cast<const float4*>(&KVs[kk * VS_LD + tx * 8]);
            *reinterpret_cast<float4*>(&vv[4]) =
                *reinterpret_cast<const float4*>(&KVs[kk * VS_LD + tx * 8 + 4]);
#pragma unroll
            for (int i = 0; i < 4; i++)
#pragma unroll
                for (int j = 0; j < 8; j++) acc[i][j] += p[i] * vv[j];
        }
    }

#pragma unroll
    for (int i = 0; i < 4; i++) {
        const float inv = 1.f / l_[i];
        const int q = qbase + ty * 4 + i;
        float* o = out + (size_t)h * SEQL * DHEAD + (size_t)q * DHEAD + tx * 8;
        *reinterpret_cast<float4*>(o) =
            make_float4(acc[i][0] * inv, acc[i][1] * inv, acc[i][2] * inv, acc[i][3] * inv);
        *reinterpret_cast<float4*>(o + 4) =
            make_float4(acc[i][4] * inv, acc[i][5] * inv, acc[i][6] * inv, acc[i][7] * inv);
    }
}

// ======================= launch =======================
extern "C" void kernel_launch(void* const* d_in, const int* in_sizes, int n_in,
                              void* d_out, int out_size) {
    const float* X  = (const float*)d_in[0];
    const float* Wq = (const float*)d_in[1];
    const float* Wk = (const float*)d_in[2];
    const float* Wv = (const float*)d_in[3];
    const float* cK = (const float*)d_in[4];
    const float* cV = (const float*)d_in[5];
    const int*   Pp = (const int*)d_in[6];

    // 0) caches -> scratch; split X; transpose+split W
    copy_cache_kernel<<<1024, 256>>>((const float4*)cK, (const float4*)cV);
    convert_X_kernel<<<2048, 256>>>((const float4*)X);
    dim3 wgrid(NMODEL / 32, NMODEL / 32, 3);
    convert_W_kernel<<<wgrid, 256>>>(Wq, Wk, Wv);

    // 1) mma.sync split-bf16 QKV projections + cache write
    cudaFuncSetAttribute(qkv_gemm_mma, cudaFuncAttributeMaxDynamicSharedMemorySize,
                         G_SMEM);
    dim3 ggrid(SEQL / GBM, NMODEL / GBN, 3);
    qkv_gemm_mma<<<ggrid, 256, G_SMEM>>>(Pp);

    // 2) attention (fp32 SIMT, unchanged)
    cudaFuncSetAttribute(attn_kernel, cudaFuncAttributeMaxDynamicSharedMemorySize,
                         ATT_SMEM_BYTES);
    dim3 agrid(SEQL / AT_BQ, HEADS);
    attn_kernel<<<agrid, 256, ATT_SMEM_BYTES>>>((float*)d_out);
}

// round 4
// speedup vs baseline: 3.2495x; 2.2492x over previous
#include <cuda_runtime.h>
#include <cuda_bf16.h>
#include <cstdint>

// Problem dims (fixed by the reference)
#define SEQL   2048
#define NMODEL 4096
#define HEADS  32
#define DHEAD  128
#define MCACHE 4096

// ======================= family-portable PTX helpers =======================
__device__ __forceinline__ uint32_t smem_to_u32(const void* p) {
    uint32_t a;
    asm("{ .reg .u64 t; cvta.to.shared.u64 t, %1; cvt.u32.u64 %0, t; }"
        : "=r"(a) : "l"(p));
    return a;
}
__device__ __forceinline__ void mma_bf16(float* c, const uint32_t* a, const uint32_t* b) {
    asm volatile(
        "mma.sync.aligned.m16n8k16.row.col.f32.bf16.bf16.f32 "
        "{%0,%1,%2,%3}, {%4,%5,%6,%7}, {%8,%9}, {%0,%1,%2,%3};"
        : "+f"(c[0]), "+f"(c[1]), "+f"(c[2]), "+f"(c[3])
        : "r"(a[0]), "r"(a[1]), "r"(a[2]), "r"(a[3]), "r"(b[0]), "r"(b[1]));
}
__device__ __forceinline__ void ldmat4(uint32_t* r, uint32_t addr) {
    asm volatile("ldmatrix.sync.aligned.m8n8.x4.shared.b16 {%0,%1,%2,%3}, [%4];"
        : "=r"(r[0]), "=r"(r[1]), "=r"(r[2]), "=r"(r[3]) : "r"(addr));
}
__device__ __forceinline__ void cpasync16(uint32_t dst, const void* src) {
    asm volatile("cp.async.cg.shared.global [%0], [%1], 16;" :: "r"(dst), "l"(src));
}
#define CP_COMMIT() asm volatile("cp.async.commit_group;" ::: "memory")
#define CP_WAIT(n)  asm volatile("cp.async.wait_group %0;" :: "n"(n) : "memory")

// pack two f32 -> bf16x2 register (low half = first arg)
__device__ __forceinline__ uint32_t packbf2(float lo, float hi) {
    uint32_t r;
    asm("cvt.rn.bf16x2.f32 %0, %1, %2;" : "=r"(r) : "f"(hi), "f"(lo));
    return r;
}
__device__ __forceinline__ float bflowf(uint32_t u)  { return __uint_as_float(u << 16); }
__device__ __forceinline__ float bfhighf(uint32_t u) { return __uint_as_float(u & 0xFFFF0000u); }

// ======================= scratch (device globals) =======================
__device__ __nv_bfloat16 g_Qhi[(size_t)HEADS * SEQL * DHEAD];
__device__ __nv_bfloat16 g_Qlo[(size_t)HEADS * SEQL * DHEAD];
__device__ __nv_bfloat16 g_Khi[(size_t)HEADS * MCACHE * DHEAD];
__device__ __nv_bfloat16 g_Klo[(size_t)HEADS * MCACHE * DHEAD];
__device__ __nv_bfloat16 g_Vthi[(size_t)HEADS * DHEAD * MCACHE];  // [h][d][m]
__device__ __nv_bfloat16 g_Vtlo[(size_t)HEADS * DHEAD * MCACHE];
__device__ __nv_bfloat16 g_Xhi[(size_t)SEQL * NMODEL];
__device__ __nv_bfloat16 g_Xlo[(size_t)SEQL * NMODEL];
__device__ __nv_bfloat16 g_Whi[3][(size_t)NMODEL * NMODEL];  // transposed: [n][k]
__device__ __nv_bfloat16 g_Wlo[3][(size_t)NMODEL * NMODEL];

// ======================= 0a) split cache_K elementwise =======================
__global__ void convert_cacheK(const float4* __restrict__ cK) {
    const int n = HEADS * MCACHE * DHEAD / 4;
    __nv_bfloat162* Hi = reinterpret_cast<__nv_bfloat162*>(g_Khi);
    __nv_bfloat162* Lo = reinterpret_cast<__nv_bfloat162*>(g_Klo);
    for (int i = blockIdx.x * blockDim.x + threadIdx.x; i < n;
         i += gridDim.x * blockDim.x) {
        float4 v = cK[i];
        __nv_bfloat16 h0 = __float2bfloat16(v.x), h1 = __float2bfloat16(v.y);
        __nv_bfloat16 h2 = __float2bfloat16(v.z), h3 = __float2bfloat16(v.w);
        Hi[2 * i]     = __nv_bfloat162(h0, h1);
        Hi[2 * i + 1] = __nv_bfloat162(h2, h3);
        Lo[2 * i]     = __nv_bfloat162(__float2bfloat16(v.x - __bfloat162float(h0)),
                                       __float2bfloat16(v.y - __bfloat162float(h1)));
        Lo[2 * i + 1] = __nv_bfloat162(__float2bfloat16(v.z - __bfloat162float(h2)),
                                       __float2bfloat16(v.w - __bfloat162float(h3)));
    }
}

// ======================= 0b) transpose + split cache_V =======================
__global__ void __launch_bounds__(256)
convert_cacheV(const float* __restrict__ cV) {
    __shared__ float tile[32][33];
    const int h  = blockIdx.z;
    const int m0 = blockIdx.x * 32;
    const int d0 = blockIdx.y * 32;
    const int t = threadIdx.x;
    const int tx = t & 31, ty = t >> 5;
#pragma unroll
    for (int i = 0; i < 4; i++)
        tile[ty + 8 * i][tx] =
            cV[((size_t)h * MCACHE + m0 + ty + 8 * i) * DHEAD + d0 + tx];
    __syncthreads();
#pragma unroll
    for (int i = 0; i < 4; i++) {
        const float v = tile[tx][ty + 8 * i];
        const __nv_bfloat16 hh = __float2bfloat16(v);
        const size_t o = ((size_t)h * DHEAD + d0 + ty + 8 * i) * MCACHE + m0 + tx;
        g_Vthi[o] = hh;
        g_Vtlo[o] = __float2bfloat16(v - __bfloat162float(hh));
    }
}

// ======================= 0c) split X =======================
__global__ void convert_X_kernel(const float4* __restrict__ X) {
    const int n = SEQL * NMODEL / 4;
    __nv_bfloat162* Hi = reinterpret_cast<__nv_bfloat162*>(g_Xhi);
    __nv_bfloat162* Lo = reinterpret_cast<__nv_bfloat162*>(g_Xlo);
    for (int i = blockIdx.x * blockDim.x + threadIdx.x; i < n;
         i += gridDim.x * blockDim.x) {
        float4 v = X[i];
        __nv_bfloat16 h0 = __float2bfloat16(v.x), h1 = __float2bfloat16(v.y);
        __nv_bfloat16 h2 = __float2bfloat16(v.z), h3 = __float2bfloat16(v.w);
        Hi[2 * i]     = __nv_bfloat162(h0, h1);
        Hi[2 * i + 1] = __nv_bfloat162(h2, h3);
        Lo[2 * i]     = __nv_bfloat162(__float2bfloat16(v.x - __bfloat162float(h0)),
                                       __float2bfloat16(v.y - __bfloat162float(h1)));
        Lo[2 * i + 1] = __nv_bfloat162(__float2bfloat16(v.z - __bfloat162float(h2)),
                                       __float2bfloat16(v.w - __bfloat162float(h3)));
    }
}

// ======================= 0d) transpose + split W =======================
__global__ void __launch_bounds__(256)
convert_W_kernel(const float* __restrict__ Wq,
                 const float* __restrict__ Wk,
                 const float* __restrict__ Wv) {
    __shared__ float tile[32][33];
    const int z = blockIdx.z;
    const float* __restrict__ W = (z == 0) ? Wq : ((z == 1) ? Wk : Wv);
    const int n0 = blockIdx.x * 32;
    const int k0 = blockIdx.y * 32;
    const int t = threadIdx.x;
    const int tx = t & 31, ty = t >> 5;
#pragma unroll
    for (int i = 0; i < 4; i++)
        tile[ty + 8 * i][tx] = W[(size_t)(k0 + ty + 8 * i) * NMODEL + n0 + tx];
    __syncthreads();
    __nv_bfloat16* Hi = g_Whi[z];
    __nv_bfloat16* Lo = g_Wlo[z];
#pragma unroll
    for (int i = 0; i < 4; i++) {
        const float v = tile[tx][ty + 8 * i];
        const __nv_bfloat16 h = __float2bfloat16(v);
        const size_t o = (size_t)(n0 + ty + 8 * i) * NMODEL + k0 + tx;
        Hi[o] = h;
        Lo[o] = __float2bfloat16(v - __bfloat162float(h));
    }
}

// ======================= 1) split-bf16 mma.sync QKV GEMM =======================
#define GBM 128
#define GBN 128
#define GBK 32
#define G_ITERS (NMODEL / GBK)
#define G_STAGE 32768
#define G_SMEM  (2 * G_STAGE)

// smem chunk swizzle for 64B rows (4 chunks)
#define SWZ(row, ch) ((uint32_t)((row) * 64 + ((((ch) ^ (((row) >> 1) & 3))) << 4)))
// fp32 staging swizzle (128 floats per row)
#define SWZ4(m, d) ((uint32_t)((m) * 128 + ((d) ^ ((m) & 31))))

__global__ void __launch_bounds__(256, 1)
qkv_gemm_mma(const int* __restrict__ Pp) {
    extern __shared__ char smg[];
    const uint32_t sb = smem_to_u32(smg);
    const int t = threadIdx.x, lane = t & 31, wid = t >> 5;
    const int mt = blockIdx.x;
    const int nt = blockIdx.y;
    const int z  = blockIdx.z;
    const int wm = wid & 1;
    const int wn = wid >> 1;

    const __nv_bfloat16* __restrict__ Ah = g_Xhi + (size_t)(mt * GBM) * NMODEL;
    const __nv_bfloat16* __restrict__ Al = g_Xlo + (size_t)(mt * GBM) * NMODEL;
    const __nv_bfloat16* __restrict__ Bh = g_Whi[z] + (size_t)(nt * GBN) * NMODEL;
    const __nv_bfloat16* __restrict__ Bl = g_Wlo[z] + (size_t)(nt * GBN) * NMODEL;

    float acc[4][4][4];
#pragma unroll
    for (int i = 0; i < 4; i++)
#pragma unroll
        for (int j = 0; j < 4; j++)
#pragma unroll
            for (int r = 0; r < 4; r++) acc[i][j][r] = 0.f;

    const int r0 = t >> 2, c0 = t & 3;
    const int r1 = (t + 256) >> 2, c1 = t & 3;

    {
        const uint32_t stg = sb;
        size_t ga0 = (size_t)r0 * NMODEL + c0 * 8;
        size_t ga1 = (size_t)r1 * NMODEL + c1 * 8;
        cpasync16(stg + SWZ(r0, c0), Ah + ga0);
        cpasync16(stg + SWZ(r1, c1), Ah + ga1);
        cpasync16(stg + 8192 + SWZ(r0, c0), Al + ga0);
        cpasync16(stg + 8192 + SWZ(r1, c1), Al + ga1);
        cpasync16(stg + 16384 + SWZ(r0, c0), Bh + ga0);
        cpasync16(stg + 16384 + SWZ(r1, c1), Bh + ga1);
        cpasync16(stg + 24576 + SWZ(r0, c0), Bl + ga0);
        cpasync16(stg + 24576 + SWZ(r1, c1), Bl + ga1);
        CP_COMMIT();
    }

    const int rowA = wm * 64 + (lane & 7) + ((lane >> 3) & 1) * 8;
    const int chA  = (lane >> 4);
    const int rowB = wn * 32 + (lane & 7) + ((lane & 16) ? 8 : 0);
    const int chB  = ((lane >> 3) & 1);

    for (int c = 0; c < G_ITERS; ++c) {
        if (c + 1 < G_ITERS) {
            const int k0 = (c + 1) * GBK;
            const uint32_t stg = sb + ((c + 1) & 1) * G_STAGE;
            size_t ga0 = (size_t)r0 * NMODEL + k0 + c0 * 8;
            size_t ga1 = (size_t)r1 * NMODEL + k0 + c1 * 8;
            cpasync16(stg + SWZ(r0, c0), Ah + ga0);
            cpasync16(stg + SWZ(r1, c1), Ah + ga1);
            cpasync16(stg + 8192 + SWZ(r0, c0), Al + ga0);
            cpasync16(stg + 8192 + SWZ(r1, c1), Al + ga1);
            cpasync16(stg + 16384 + SWZ(r0, c0), Bh + ga0);
            cpasync16(stg + 16384 + SWZ(r1, c1), Bh + ga1);
            cpasync16(stg + 24576 + SWZ(r0, c0), Bl + ga0);
            cpasync16(stg + 24576 + SWZ(r1, c1), Bl + ga1);
            CP_COMMIT();
            CP_WAIT(1);
        } else {
            CP_WAIT(0);
        }
        __syncthreads();

        const uint32_t sA = sb + (c & 1) * G_STAGE;
        const uint32_t sB = sA + 16384;
#pragma unroll
        for (int g = 0; g < 2; ++g) {
            uint32_t ah[4][4], al[4][4], bh[2][4], bl[2][4];
#pragma unroll
            for (int mi = 0; mi < 4; ++mi) {
                const uint32_t ad = sA + SWZ(rowA + mi * 16, 2 * g + chA);
                ldmat4(ah[mi], ad);
                ldmat4(al[mi], ad + 8192);
            }
#pragma unroll
            for (int bj = 0; bj < 2; ++bj) {
                const uint32_t ad = sB + SWZ(rowB + bj * 16, 2 * g + chB);
                ldmat4(bh[bj], ad);
                ldmat4(bl[bj], ad + 8192);
            }
#pragma unroll
            for (int mi = 0; mi < 4; ++mi)
#pragma unroll
                for (int nj = 0; nj < 4; ++nj) {
                    const uint32_t* bhp = &bh[nj >> 1][(nj & 1) * 2];
                    const uint32_t* blp = &bl[nj >> 1][(nj & 1) * 2];
                    mma_bf16(acc[mi][nj], ah[mi], bhp);
                    mma_bf16(acc[mi][nj], ah[mi], blp);
                    mma_bf16(acc[mi][nj], al[mi], bhp);
                }
        }
        __syncthreads();
    }

    // ---- epilogue: emit bf16 hi/lo ----
    const int P = *Pp;
    const int qr = lane >> 2, qc = (lane & 3) * 2;

    if (z != 2) {
        __nv_bfloat16* Dhi = (z == 0) ? g_Qhi : g_Khi;
        __nv_bfloat16* Dlo = (z == 0) ? g_Qlo : g_Klo;
        const int rows  = (z == 0) ? SEQL : MCACHE;
        const int rbase = (z == 0) ? 0 : P;
#pragma unroll
        for (int mi = 0; mi < 4; ++mi)
#pragma unroll
            for (int nj = 0; nj < 4; ++nj) {
                const int m0 = mt * GBM + wm * 64 + mi * 16 + qr;
                const int n  = nt * GBN + wn * 32 + nj * 8 + qc;
                const int h = n >> 7, d0 = n & 127;
#pragma unroll
                for (int hv = 0; hv < 2; ++hv) {
                    const float v0 = acc[mi][nj][2 * hv];
                    const float v1 = acc[mi][nj][2 * hv + 1];
                    const uint32_t hi = packbf2(v0, v1);
                    const uint32_t lo = packbf2(v0 - bflowf(hi), v1 - bfhighf(hi));
                    const size_t o = ((size_t)h * rows + rbase + m0 + 8 * hv) * DHEAD + d0;
                    *reinterpret_cast<uint32_t*>(Dhi + o) = hi;
                    *reinterpret_cast<uint32_t*>(Dlo + o) = lo;
                }
            }
    } else {
        // V: stage fp32 tile, transpose to g_Vt[h=nt][d][m]
        float* st = reinterpret_cast<float*>(smg);
#pragma unroll
        for (int mi = 0; mi < 4; ++mi)
#pragma unroll
            for (int nj = 0; nj < 4; ++nj) {
                const int ml = wm * 64 + mi * 16 + qr;
                const int nl = wn * 32 + nj * 8 + qc;
                st[SWZ4(ml, nl)]         = acc[mi][nj][0];
                st[SWZ4(ml, nl + 1)]     = acc[mi][nj][1];
                st[SWZ4(ml + 8, nl)]     = acc[mi][nj][2];
                st[SWZ4(ml + 8, nl + 1)] = acc[mi][nj][3];
            }
        __syncthreads();
        const int d  = t >> 1;
        const int ms = (t & 1) * 64;
        const size_t ob = ((size_t)nt * DHEAD + d) * MCACHE + P + mt * GBM + ms;
#pragma unroll
        for (int mm = 0; mm < 64; mm += 2) {
            const float v0 = st[SWZ4(ms + mm, d)];
            const float v1 = st[SWZ4(ms + mm + 1, d)];
            const uint32_t hi = packbf2(v0, v1);
            const uint32_t lo = packbf2(v0 - bflowf(hi), v1 - bfhighf(hi));
            *reinterpret_cast<uint32_t*>(g_Vthi + ob + mm) = hi;
            *reinterpret_cast<uint32_t*>(g_Vtlo + ob + mm) = lo;
        }
    }
}

// ======================= 2) tensor-core flash attention =======================
// CTA: 128 q rows x 1 head. 8 warps, each owns 16 q rows, all 128 kv cols.
// smem: Q hi/lo (resident) + K hi/lo + Vt hi/lo tiles, 256B rows, swizzled.
#define ABQ   128
#define ABKV  128
#define NKT   (MCACHE / ABKV)   // 32
#define SWB(row, ch) ((uint32_t)((row) * 256 + ((((ch) ^ ((row) & 7))) << 4)))
#define AQ_HI 0
#define AQ_LO 32768
#define AK_HI 65536
#define AK_LO 98304
#define AV_HI 131072
#define AV_LO 163840
#define A_SMEM 196608

// issue one 128x128 bf16 tile pair (hi+lo) via cp.async (16 per thread)
__device__ __forceinline__ void issue_tile(uint32_t smhi, uint32_t smlo,
                                           const __nv_bfloat16* ghi,
                                           const __nv_bfloat16* glo,
                                           size_t rowstride, int t) {
#pragma unroll
    for (int i = 0; i < 8; ++i) {
        const int idx = t + i * 256;
        const int row = idx >> 4, ch = idx & 15;
        const size_t go = (size_t)row * rowstride + ch * 8;
        const uint32_t so = SWB(row, ch);
        cpasync16(smhi + so, ghi + go);
        cpasync16(smlo + so, glo + go);
    }
}

__global__ void __launch_bounds__(256, 1)
attn_tc(float* __restrict__ out) {
    extern __shared__ char sma[];
    const uint32_t sb = smem_to_u32(sma);
    const int t = threadIdx.x, lane = t & 31, wid = t >> 5;
    const int h  = blockIdx.y;
    const int q0 = blockIdx.x * ABQ;
    const int q0w = wid * 16;

    const __nv_bfloat16* __restrict__ Qh = g_Qhi + ((size_t)h * SEQL + q0) * DHEAD;
    const __nv_bfloat16* __restrict__ Ql = g_Qlo + ((size_t)h * SEQL + q0) * DHEAD;
    const __nv_bfloat16* __restrict__ Kh = g_Khi + (size_t)h * MCACHE * DHEAD;
    const __nv_bfloat16* __restrict__ Kl = g_Klo + (size_t)h * MCACHE * DHEAD;
    const __nv_bfloat16* __restrict__ Vh = g_Vthi + (size_t)h * DHEAD * MCACHE;
    const __nv_bfloat16* __restrict__ Vl = g_Vtlo + (size_t)h * DHEAD * MCACHE;

    // prologue: Q + K0 (group), V0 (group)
    issue_tile(sb + AQ_HI, sb + AQ_LO, Qh, Ql, DHEAD, t);
    issue_tile(sb + AK_HI, sb + AK_LO, Kh, Kl, DHEAD, t);
    CP_COMMIT();
    issue_tile(sb + AV_HI, sb + AV_LO, Vh, Vl, MCACHE, t);
    CP_COMMIT();
    CP_WAIT(1);
    __syncthreads();

    const int rowA = (lane & 7) + ((lane >> 3) & 1) * 8;  // A-frag rows (q)
    const int chA  = (lane >> 4);
    const int rowB = (lane & 7) + ((lane & 16) ? 8 : 0);  // B-frag rows (n)
    const int chB  = ((lane >> 3) & 1);

    float m0 = -1e30f, m1 = -1e30f, l0 = 0.f, l1 = 0.f;
    float o[16][4];
#pragma unroll
    for (int i = 0; i < 16; i++)
#pragma unroll
        for (int r = 0; r < 4; r++) o[i][r] = 0.f;

    for (int kt = 0; kt < NKT; ++kt) {
        // ---- S = Q K^T (split-bf16, 3 MMA) ----
        float s[16][4];
#pragma unroll
        for (int i = 0; i < 16; i++)
#pragma unroll
            for (int r = 0; r < 4; r++) s[i][r] = 0.f;

#pragma unroll
        for (int ks = 0; ks < 8; ++ks) {
            uint32_t ah[4], al[4];
            const uint32_t qa = sb + SWB(q0w + rowA, 2 * ks + chA);
            ldmat4(ah, qa + AQ_HI);
            ldmat4(al, qa + AQ_LO);
#pragma unroll
            for (int bj = 0; bj < 8; ++bj) {
                uint32_t bh[4], bl[4];
                const uint32_t ka = sb + SWB(bj * 16 + rowB, 2 * ks + chB);
                ldmat4(bh, ka + AK_HI);
                ldmat4(bl, ka + AK_LO);
#pragma unroll
                for (int sub = 0; sub < 2; ++sub) {
                    float* cc = s[2 * bj + sub];
                    mma_bf16(cc, ah, &bh[2 * sub]);
                    mma_bf16(cc, ah, &bl[2 * sub]);
                    mma_bf16(cc, al, &bh[2 * sub]);
                }
            }
        }
        __syncthreads();  // K consumed
        if (kt + 1 < NKT) {
            issue_tile(sb + AK_HI, sb + AK_LO,
                       Kh + (size_t)(kt + 1) * ABKV * DHEAD,
                       Kl + (size_t)(kt + 1) * ABKV * DHEAD, DHEAD, t);
            CP_COMMIT();
        }

        // ---- online softmax (rows qr, qr+8 of warp tile) ----
        float tm0 = s[0][0], tm1 = s[0][2];
#pragma unroll
        for (int nj = 0; nj < 16; ++nj) {
            tm0 = fmaxf(tm0, fmaxf(s[nj][0], s[nj][1]));
            tm1 = fmaxf(tm1, fmaxf(s[nj][2], s[nj][3]));
        }
        tm0 = fmaxf(tm0, __shfl_xor_sync(0xffffffffu, tm0, 1));
        tm0 = fmaxf(tm0, __shfl_xor_sync(0xffffffffu, tm0, 2));
        tm1 = fmaxf(tm1, __shfl_xor_sync(0xffffffffu, tm1, 1));
        tm1 = fmaxf(tm1, __shfl_xor_sync(0xffffffffu, tm1, 2));
        const float nm0 = fmaxf(m0, tm0), nm1 = fmaxf(m1, tm1);
        const float cr0 = __expf(m0 - nm0), cr1 = __expf(m1 - nm1);
        float sum0 = 0.f, sum1 = 0.f;
#pragma unroll
        for (int nj = 0; nj < 16; ++nj) {
            s[nj][0] = __expf(s[nj][0] - nm0); sum0 += s[nj][0];
            s[nj][1] = __expf(s[nj][1] - nm0); sum0 += s[nj][1];
            s[nj][2] = __expf(s[nj][2] - nm1); sum1 += s[nj][2];
            s[nj][3] = __expf(s[nj][3] - nm1); sum1 += s[nj][3];
        }
        sum0 += __shfl_xor_sync(0xffffffffu, sum0, 1);
        sum0 += __shfl_xor_sync(0xffffffffu, sum0, 2);
        sum1 += __shfl_xor_sync(0xffffffffu, sum1, 1);
        sum1 += __shfl_xor_sync(0xffffffffu, sum1, 2);
        l0 = l0 * cr0 + sum0;
        l1 = l1 * cr1 + sum1;
        m0 = nm0; m1 = nm1;
#pragma unroll
        for (int nj = 0; nj < 16; ++nj) {
            o[nj][0] *= cr0; o[nj][1] *= cr0;
            o[nj][2] *= cr1; o[nj][3] *= cr1;
        }

        // ---- wait V, then O += P V ----
        CP_WAIT(1);   // newest (K_{t+1}) may still be in flight; V_t done
        __syncthreads();

#pragma unroll
        for (int j = 0; j < 8; ++j) {
            // P A-fragments from S accumulators (hi + residual lo)
            uint32_t aph[4], apl[4];
            {
                const float p00 = s[2 * j][0],     p01 = s[2 * j][1];
                const float p10 = s[2 * j][2],     p11 = s[2 * j][3];
                const float p20 = s[2 * j + 1][0], p21 = s[2 * j + 1][1];
                const float p30 = s[2 * j + 1][2], p31 = s[2 * j + 1][3];
                aph[0] = packbf2(p00, p01);
                aph[1] = packbf2(p10, p11);
                aph[2] = packbf2(p20, p21);
                aph[3] = packbf2(p30, p31);
                apl[0] = packbf2(p00 - bflowf(aph[0]), p01 - bfhighf(aph[0]));
                apl[1] = packbf2(p10 - bflowf(aph[1]), p11 - bfhighf(aph[1]));
                apl[2] = packbf2(p20 - bflowf(aph[2]), p21 - bfhighf(aph[2]));
                apl[3] = packbf2(p30 - bflowf(aph[3]), p31 - bfhighf(aph[3]));
            }
#pragma unroll
            for (int bj = 0; bj < 8; ++bj) {
                uint32_t vh[4], vl[4];
                const uint32_t va = sb + SWB(bj * 16 + rowB, 2 * j + chB);
                ldmat4(vh, va + AV_HI);
                ldmat4(vl, va + AV_LO);
#pragma unroll
                for (int sub = 0; sub < 2; ++sub) {
                    float* cc = o[2 * bj + sub];
                    mma_bf16(cc, aph, &vh[2 * sub]);
                    mma_bf16(cc, aph, &vl[2 * sub]);
                    mma_bf16(cc, apl, &vh[2 * sub]);
                }
            }
        }
        __syncthreads();  // V consumed
        if (kt + 1 < NKT) {
            issue_tile(sb + AV_HI, sb + AV_LO,
                       Vh + (size_t)(kt + 1) * ABKV,
                       Vl + (size_t)(kt + 1) * ABKV, MCACHE, t);
            CP_COMMIT();
            CP_WAIT(1);   // K_{t+1} done; V_{t+1} in flight
            __syncthreads();
        }
    }

    // ---- normalize + write ----
    const float inv0 = __fdividef(1.f, l0);
    const float inv1 = __fdividef(1.f, l1);
    const int row0 = q0 + q0w + (lane >> 2);
    const int qc = (lane & 3) * 2;
#pragma unroll
    for (int nj = 0; nj < 16; ++nj) {
        const int d0 = nj * 8 + qc;
        float* p0 = out + ((size_t)h * SEQL + row0) * DHEAD + d0;
        float* p1 = out + ((size_t)h * SEQL + row0 + 8) * DHEAD + d0;
        *reinterpret_cast<float2*>(p0) = make_float2(o[nj][0] * inv0, o[nj][1] * inv0);
        *reinterpret_cast<float2*>(p1) = make_float2(o[nj][2] * inv1, o[nj][3] * inv1);
    }
}

// ======================= launch =======================
extern "C" void kernel_launch(void* const* d_in, const int* in_sizes, int n_in,
                              void* d_out, int out_size) {
    const float* X  = (const float*)d_in[0];
    const float* Wq = (const float*)d_in[1];
    const float* Wk = (const float*)d_in[2];
    const float* Wv = (const float*)d_in[3];
    const float* cK = (const float*)d_in[4];
    const float* cV = (const float*)d_in[5];
    const int*   Pp = (const int*)d_in[6];

    // 0) conversions
    convert_cacheK<<<1024, 256>>>((const float4*)cK);
    dim3 vgrid(MCACHE / 32, DHEAD / 32, HEADS);
    convert_cacheV<<<vgrid, 256>>>(cV);
    convert_X_kernel<<<2048, 256>>>((const float4*)X);
    dim3 wgrid(NMODEL / 32, NMODEL / 32, 3);
    convert_W_kernel<<<wgrid, 256>>>(Wq, Wk, Wv);

    // 1) QKV projections (tensor) -> bf16 hi/lo Q/K/Vt
    cudaFuncSetAttribute(qkv_gemm_mma, cudaFuncAttributeMaxDynamicSharedMemorySize,
                         G_SMEM);
    dim3 ggrid(SEQL / GBM, NMODEL / GBN, 3);
    qkv_gemm_mma<<<ggrid, 256, G_SMEM>>>(Pp);

    // 2) tensor-core flash attention
    cudaFuncSetAttribute(attn_tc, cudaFuncAttributeMaxDynamicSharedMemorySize,
                         A_SMEM);
    dim3 agrid(SEQL / ABQ, HEADS);
    attn_tc<<<agrid, 256, A_SMEM>>>((float*)d_out);
}